// round 4
// baseline (speedup 1.0000x reference)
#include <cuda_runtime.h>
#include <cstdint>

#define D 128
#define TQ 128
#define TK 64
#define NTHREADS 256
#define NGLOBAL 100
#define LPRE 2048

// smem strides chosen so fragment v2 (64-bit) LDS are conflict-free:
// bank-delta = (stride mod 32) * row-delta + col-delta; stride ≡ 8 (mod 32).
#define QS_STRIDE 136
#define KS_STRIDE 136
#define VF_STRIDE 264   // float stride of V pair-packed rows (132 u64)
#define PT_STRIDE 72

#define QS_OFF 0
#define KS_OFF (TQ * QS_STRIDE)                // 17408
#define VF_OFF (KS_OFF + TK * KS_STRIDE)       // 26112 (even -> 8B aligned)
#define PT_OFF (VF_OFF + 32 * VF_STRIDE)       // 34560
#define SMEM_FLOATS (PT_OFF + TQ * PT_STRIDE)  // 43776 floats = 171 KB

typedef unsigned int u32;

__device__ __forceinline__ u32 to_tf32(float x) {
    u32 r;
    asm("cvt.rna.tf32.f32 %0, %1;" : "=r"(r) : "f"(x));
    return r;
}

__device__ __forceinline__ void mma_tf32(float c[4], u32 a0, u32 a1, u32 a2, u32 a3,
                                         u32 b0, u32 b1) {
    asm volatile(
        "mma.sync.aligned.m16n8k8.row.col.f32.tf32.tf32.f32 "
        "{%0,%1,%2,%3}, {%4,%5,%6,%7}, {%8,%9}, {%0,%1,%2,%3};"
        : "+f"(c[0]), "+f"(c[1]), "+f"(c[2]), "+f"(c[3])
        : "r"(a0), "r"(a1), "r"(a2), "r"(a3), "r"(b0), "r"(b1));
}

// column permutation: within each 8-dim group, fragment positions tig and tig+4
// become physically adjacent -> v2 LDS for A/B fragments.
__device__ __forceinline__ int phys_col(int d) {
    return (d & ~7) | ((d & 3) << 1) | ((d >> 2) & 1);
}

// fast exp2 for x <= 0 (poly deg-6, rel err ~1e-5). Handles -1e30 sentinel -> ~0.
__device__ __forceinline__ float fexp2(float x) {
    x = fmaxf(x, -126.0f);
    int ni = __float2int_rd(x);
    float f = x - (float)ni;
    float p = 1.54035304e-4f;
    p = fmaf(p, f, 1.33335581e-3f);
    p = fmaf(p, f, 9.61812911e-3f);
    p = fmaf(p, f, 5.55041087e-2f);
    p = fmaf(p, f, 2.40226507e-1f);
    p = fmaf(p, f, 6.93147181e-1f);
    p = fmaf(p, f, 1.0f);
    return __int_as_float(__float_as_int(p) + (ni << 23));
}

__global__ void __launch_bounds__(NTHREADS, 1)
lminf_kernel(const float* __restrict__ Q, const float* __restrict__ K,
             const float* __restrict__ V, float* __restrict__ O, int S) {
    extern __shared__ float sm[];
    float* Qs = sm + QS_OFF;
    float* Ks = sm + KS_OFF;
    float* Vf = sm + VF_OFF;   // pair-packed: Vf[rv*264 + 2*d + half]
    float* Pt = sm + PT_OFF;

    const int b   = blockIdx.y;
    const int q0  = blockIdx.x * TQ;
    const int tid = threadIdx.x;
    const int w    = tid >> 5;
    const int lane = tid & 31;
    const int g    = lane >> 2;   // group id 0..7
    const int tig  = lane & 3;    // thread-in-group 0..3
    const int qb   = 16 * w;      // warp's q-row base within tile

    const float* Qg = Q + (size_t)b * S * D;
    const float* Kg = K + (size_t)b * S * D;
    const float* Vg = V + (size_t)b * S * D;

    const float QSCALE = 0.0883883476f * 1.44269504089f;  // 1/sqrt(128) * log2(e)
    const float LOG2E  = 1.44269504089f;

    // ---- load Q tile: tf32-rounded, pre-scaled, column-permuted ----
    {
        const float4* src = (const float4*)(Qg + (size_t)q0 * D);
        #pragma unroll
        for (int it = 0; it < (TQ * 32) / NTHREADS; it++) {
            int idx = tid + it * NTHREADS;
            int row = idx >> 5, f4 = idx & 31;
            float4 v = src[idx];
            float vv[4] = {v.x * QSCALE, v.y * QSCALE, v.z * QSCALE, v.w * QSCALE};
            int d0 = f4 * 4;
            #pragma unroll
            for (int e = 0; e < 4; e++)
                Qs[row * QS_STRIDE + phys_col(d0 + e)] = __uint_as_float(to_tf32(vv[e]));
        }
    }

    float co[16][4];              // O accum: 16 dim-tiles x {r0d0,r0d1,r1d0,r1d1}
    #pragma unroll
    for (int nt = 0; nt < 16; nt++)
        #pragma unroll
        for (int e = 0; e < 4; e++) co[nt][e] = 0.0f;
    float m0 = -1e30f, m1 = -1e30f, l0 = 0.0f, l1 = 0.0f;

    const int i0 = q0 + qb + g;
    const int i1 = i0 + 8;

    const int kend = q0 + TQ;
    for (int k0 = 0; k0 < kend; k0 += TK) {
        if (k0 >= NGLOBAL && (k0 + TK) <= (q0 - LPRE + 1)) continue;

        __syncthreads();   // previous tile's PV done reading Vf/Ks
        // ---- load K (permuted) + V (pair-packed) tiles, tf32-rounded ----
        {
            const float4* ksrc = (const float4*)(Kg + (size_t)k0 * D);
            const float4* vsrc = (const float4*)(Vg + (size_t)k0 * D);
            #pragma unroll
            for (int it = 0; it < (TK * 32) / NTHREADS; it++) {
                int idx = tid + it * NTHREADS;
                int row = idx >> 5, f4 = idx & 31;
                int d0 = f4 * 4;
                float4 kv = ksrc[idx];
                float kk4[4] = {kv.x, kv.y, kv.z, kv.w};
                #pragma unroll
                for (int e = 0; e < 4; e++)
                    Ks[row * KS_STRIDE + phys_col(d0 + e)] = __uint_as_float(to_tf32(kk4[e]));
                float4 vv = vsrc[idx];
                float vv4[4] = {vv.x, vv.y, vv.z, vv.w};
                int rv   = 4 * (row >> 3) + (row & 3);
                int half = (row >> 2) & 1;
                #pragma unroll
                for (int e = 0; e < 4; e++)
                    Vf[rv * VF_STRIDE + 2 * (d0 + e) + half] = __uint_as_float(to_tf32(vv4[e]));
            }
        }
        __syncthreads();

        // ---- QK^T: 16x64 per warp via 128 HMMA tf32 ----
        float c[8][4];
        #pragma unroll
        for (int nt = 0; nt < 8; nt++)
            #pragma unroll
            for (int e = 0; e < 4; e++) c[nt][e] = 0.0f;

        #pragma unroll
        for (int kk = 0; kk < 16; kk++) {
            uint2 a02 = *(const uint2*)&Qs[(qb + g)     * QS_STRIDE + 8 * kk + 2 * tig];
            uint2 a13 = *(const uint2*)&Qs[(qb + g + 8) * QS_STRIDE + 8 * kk + 2 * tig];
            #pragma unroll
            for (int nt = 0; nt < 8; nt++) {
                uint2 b01 = *(const uint2*)&Ks[(8 * nt + g) * KS_STRIDE + 8 * kk + 2 * tig];
                mma_tf32(c[nt], a02.x, a13.x, a02.y, a13.y, b01.x, b01.y);
            }
        }

        // ---- mask + bias + online softmax on fragments ----
        float mx0 = -1e30f, mx1 = -1e30f;
        #pragma unroll
        for (int nt = 0; nt < 8; nt++) {
            int j0 = k0 + 8 * nt + 2 * tig;
            int j1 = j0 + 1;
            bool ok00 = (j0 <= i0) && ((j0 < NGLOBAL) || (j0 >= i0 - (LPRE - 1)));
            bool ok01 = (j1 <= i0) && ((j1 < NGLOBAL) || (j1 >= i0 - (LPRE - 1)));
            bool ok10 = (j0 <= i1) && ((j0 < NGLOBAL) || (j0 >= i1 - (LPRE - 1)));
            bool ok11 = (j1 <= i1) && ((j1 < NGLOBAL) || (j1 >= i1 - (LPRE - 1)));
            c[nt][0] = ok00 ? fmaf((float)(j0 - i0), LOG2E, c[nt][0]) : -1e30f;
            c[nt][1] = ok01 ? fmaf((float)(j1 - i0), LOG2E, c[nt][1]) : -1e30f;
            c[nt][2] = ok10 ? fmaf((float)(j0 - i1), LOG2E, c[nt][2]) : -1e30f;
            c[nt][3] = ok11 ? fmaf((float)(j1 - i1), LOG2E, c[nt][3]) : -1e30f;
            mx0 = fmaxf(mx0, fmaxf(c[nt][0], c[nt][1]));
            mx1 = fmaxf(mx1, fmaxf(c[nt][2], c[nt][3]));
        }
        mx0 = fmaxf(mx0, __shfl_xor_sync(0xffffffffu, mx0, 1));
        mx0 = fmaxf(mx0, __shfl_xor_sync(0xffffffffu, mx0, 2));
        mx1 = fmaxf(mx1, __shfl_xor_sync(0xffffffffu, mx1, 1));
        mx1 = fmaxf(mx1, __shfl_xor_sync(0xffffffffu, mx1, 2));

        float mn0 = fmaxf(m0, mx0), mn1 = fmaxf(m1, mx1);
        float sc0 = fexp2(m0 - mn0), sc1 = fexp2(m1 - mn1);
        float ps0 = 0.0f, ps1 = 0.0f;
        #pragma unroll
        for (int nt = 0; nt < 8; nt++) {
            #pragma unroll
            for (int e = 0; e < 2; e++) {
                int jl = 8 * nt + 2 * tig + e;
                int pc = phys_col(jl);
                u32 pb0 = to_tf32(fexp2(c[nt][e]     - mn0));
                u32 pb1 = to_tf32(fexp2(c[nt][2 + e] - mn1));
                ps0 += __uint_as_float(pb0);
                ps1 += __uint_as_float(pb1);
                Pt[(qb + g)     * PT_STRIDE + pc] = __uint_as_float(pb0);
                Pt[(qb + g + 8) * PT_STRIDE + pc] = __uint_as_float(pb1);
            }
        }
        ps0 += __shfl_xor_sync(0xffffffffu, ps0, 1);
        ps0 += __shfl_xor_sync(0xffffffffu, ps0, 2);
        ps1 += __shfl_xor_sync(0xffffffffu, ps1, 1);
        ps1 += __shfl_xor_sync(0xffffffffu, ps1, 2);

        l0 = l0 * sc0 + ps0;  m0 = mn0;
        l1 = l1 * sc1 + ps1;  m1 = mn1;
        #pragma unroll
        for (int nt = 0; nt < 16; nt++) {
            co[nt][0] *= sc0; co[nt][1] *= sc0;
            co[nt][2] *= sc1; co[nt][3] *= sc1;
        }
        __syncwarp();   // P rows are warp-private: warp-level fence suffices

        // ---- P x V: 16x128 per warp via 128 HMMA tf32 ----
        #pragma unroll
        for (int kk2 = 0; kk2 < 8; kk2++) {
            uint2 a02 = *(const uint2*)&Pt[(qb + g)     * PT_STRIDE + 8 * kk2 + 2 * tig];
            uint2 a13 = *(const uint2*)&Pt[(qb + g + 8) * PT_STRIDE + 8 * kk2 + 2 * tig];
            #pragma unroll
            for (int nt = 0; nt < 16; nt++) {
                uint2 b01 = *(const uint2*)&Vf[(4 * kk2 + tig) * VF_STRIDE + 2 * (8 * nt + g)];
                mma_tf32(co[nt], a02.x, a13.x, a02.y, a13.y, b01.x, b01.y);
            }
        }
        __syncwarp();   // PV reads of Pt done before next tile overwrites it
    }

    // ---- epilogue: O = co / l ----
    float inv0 = 1.0f / l0, inv1 = 1.0f / l1;
    float2* o0 = (float2*)(O + ((size_t)b * S + i0) * D);
    float2* o1 = (float2*)(O + ((size_t)b * S + i1) * D);
    #pragma unroll
    for (int nt = 0; nt < 16; nt++) {
        o0[4 * nt + tig] = make_float2(co[nt][0] * inv0, co[nt][1] * inv0);
        o1[4 * nt + tig] = make_float2(co[nt][2] * inv1, co[nt][3] * inv1);
    }
}

extern "C" void kernel_launch(void* const* d_in, const int* in_sizes, int n_in,
                              void* d_out, int out_size) {
    const float* q = (const float*)d_in[0];
    const float* k = (const float*)d_in[1];
    const float* v = (const float*)d_in[2];
    float* o = (float*)d_out;

    const int B = 2;
    const int S = in_sizes[0] / (B * D);   // 8192

    size_t smem_bytes = (size_t)SMEM_FLOATS * sizeof(float);  // ~171 KB
    cudaFuncSetAttribute(lminf_kernel, cudaFuncAttributeMaxDynamicSharedMemorySize,
                         (int)smem_bytes);

    dim3 grid(S / TQ, B);
    lminf_kernel<<<grid, NTHREADS, smem_bytes>>>(q, k, v, o, S);
}

// round 5
// speedup vs baseline: 1.1185x; 1.1185x over previous
#include <cuda_runtime.h>
#include <cstdint>

#define D 128
#define TQ 128
#define TK 64
#define NTHREADS 256
#define NGLOBAL 100
#define LPRE 2048
#define SP 4            // key-dimension splits (flash-decoding style)
#define BMAX 2
#define SMAX 8192

// smem strides chosen so fragment v2 (64-bit) LDS are conflict-free:
// bank-delta = (stride mod 32) * row-delta + col-delta; stride ≡ 8 (mod 32).
#define QS_STRIDE 136
#define KS_STRIDE 136
#define VF_STRIDE 264   // float stride of V pair-packed rows (132 u64)
#define PT_STRIDE 72

#define QS_OFF 0
#define KS_OFF (TQ * QS_STRIDE)                // 17408
#define VF_OFF (KS_OFF + TK * KS_STRIDE)       // 26112 (even -> 8B aligned)
#define PT_OFF (VF_OFF + 32 * VF_STRIDE)       // 34560
#define SMEM_FLOATS (PT_OFF + TQ * PT_STRIDE)  // 43776 floats = 171 KB

typedef unsigned int u32;

// split-K scratch (static device globals: allocation-free)
__device__ float g_Op[(size_t)SP * BMAX * SMAX * D];   // unnormalized partial O
__device__ float g_Ml[SP * BMAX * SMAX];               // per-row running max (log2 domain)
__device__ float g_Ll[SP * BMAX * SMAX];               // per-row partial denom

__device__ __forceinline__ u32 to_tf32(float x) {
    u32 r;
    asm("cvt.rna.tf32.f32 %0, %1;" : "=r"(r) : "f"(x));
    return r;
}

__device__ __forceinline__ void mma_tf32(float c[4], u32 a0, u32 a1, u32 a2, u32 a3,
                                         u32 b0, u32 b1) {
    asm volatile(
        "mma.sync.aligned.m16n8k8.row.col.f32.tf32.tf32.f32 "
        "{%0,%1,%2,%3}, {%4,%5,%6,%7}, {%8,%9}, {%0,%1,%2,%3};"
        : "+f"(c[0]), "+f"(c[1]), "+f"(c[2]), "+f"(c[3])
        : "r"(a0), "r"(a1), "r"(a2), "r"(a3), "r"(b0), "r"(b1));
}

// column permutation: within each 8-dim group, fragment positions tig and tig+4
// become physically adjacent -> v2 LDS for A/B fragments.
__device__ __forceinline__ int phys_col(int d) {
    return (d & ~7) | ((d & 3) << 1) | ((d >> 2) & 1);
}

// fast exp2 for x <= 0 (poly deg-6, rel err ~1e-5). Handles -1e30 sentinel -> ~0.
__device__ __forceinline__ float fexp2(float x) {
    x = fmaxf(x, -126.0f);
    int ni = __float2int_rd(x);
    float f = x - (float)ni;
    float p = 1.54035304e-4f;
    p = fmaf(p, f, 1.33335581e-3f);
    p = fmaf(p, f, 9.61812911e-3f);
    p = fmaf(p, f, 5.55041087e-2f);
    p = fmaf(p, f, 2.40226507e-1f);
    p = fmaf(p, f, 6.93147181e-1f);
    p = fmaf(p, f, 1.0f);
    return __int_as_float(__float_as_int(p) + (ni << 23));
}

__global__ void __launch_bounds__(NTHREADS, 1)
lminf_kernel(const float* __restrict__ Q, const float* __restrict__ K,
             const float* __restrict__ V, int S) {
    extern __shared__ float sm[];
    float* Qs = sm + QS_OFF;
    float* Ks = sm + KS_OFF;
    float* Vf = sm + VF_OFF;   // pair-packed: Vf[rv*264 + 2*d + half]
    float* Pt = sm + PT_OFF;

    const int b   = blockIdx.y;
    const int q0  = blockIdx.x * TQ;
    const int sp  = blockIdx.z;
    const int tid = threadIdx.x;
    const int w    = tid >> 5;
    const int lane = tid & 31;
    const int g    = lane >> 2;   // group id 0..7
    const int tig  = lane & 3;    // thread-in-group 0..3
    const int qb   = 16 * w;      // warp's q-row base within tile

    const float* Qg = Q + (size_t)b * S * D;
    const float* Kg = K + (size_t)b * S * D;
    const float* Vg = V + (size_t)b * S * D;

    const float QSCALE = 0.0883883476f * 1.44269504089f;  // 1/sqrt(128) * log2(e)
    const float LOG2E  = 1.44269504089f;

    // ---- enumerate visited tiles & take this split's contiguous chunk ----
    // visited = {0,1} (global sinks) ∪ [tLoc, nTile) (local window)
    const int nTile = (q0 + TQ) / TK;
    int tLoc = 2;
    {
        int dd = q0 - (LPRE - 1) - TK;   // tile t skipped iff t>=2 && 64t <= dd
        if (dd >= 0) { int t = dd / TK + 1; if (t > 2) tLoc = t; }
    }
    const int NT  = 2 + (nTile - tLoc);
    const int it0 = (sp * NT) / SP;
    const int it1 = ((sp + 1) * NT) / SP;

    // ---- load Q tile: tf32-rounded, pre-scaled, column-permuted ----
    if (it0 < it1) {
        const float4* src = (const float4*)(Qg + (size_t)q0 * D);
        #pragma unroll
        for (int it = 0; it < (TQ * 32) / NTHREADS; it++) {
            int idx = tid + it * NTHREADS;
            int row = idx >> 5, f4 = idx & 31;
            float4 v = src[idx];
            float vv[4] = {v.x * QSCALE, v.y * QSCALE, v.z * QSCALE, v.w * QSCALE};
            int d0 = f4 * 4;
            #pragma unroll
            for (int e = 0; e < 4; e++)
                Qs[row * QS_STRIDE + phys_col(d0 + e)] = __uint_as_float(to_tf32(vv[e]));
        }
    }

    float co[16][4];              // O accum: 16 dim-tiles x {r0d0,r0d1,r1d0,r1d1}
    #pragma unroll
    for (int nt = 0; nt < 16; nt++)
        #pragma unroll
        for (int e = 0; e < 4; e++) co[nt][e] = 0.0f;
    float m0 = -1e30f, m1 = -1e30f, l0 = 0.0f, l1 = 0.0f;

    const int i0 = q0 + qb + g;
    const int i1 = i0 + 8;

    for (int it = it0; it < it1; it++) {
        const int k0 = ((it < 2) ? it : (tLoc + it - 2)) * TK;

        __syncthreads();   // previous tile's PV done reading Vf/Ks
        // ---- load K (permuted) + V (pair-packed) tiles, tf32-rounded ----
        {
            const float4* ksrc = (const float4*)(Kg + (size_t)k0 * D);
            const float4* vsrc = (const float4*)(Vg + (size_t)k0 * D);
            #pragma unroll
            for (int itl = 0; itl < (TK * 32) / NTHREADS; itl++) {
                int idx = tid + itl * NTHREADS;
                int row = idx >> 5, f4 = idx & 31;
                int d0 = f4 * 4;
                float4 kv = ksrc[idx];
                float kk4[4] = {kv.x, kv.y, kv.z, kv.w};
                #pragma unroll
                for (int e = 0; e < 4; e++)
                    Ks[row * KS_STRIDE + phys_col(d0 + e)] = __uint_as_float(to_tf32(kk4[e]));
                float4 vv = vsrc[idx];
                float vv4[4] = {vv.x, vv.y, vv.z, vv.w};
                int rv   = 4 * (row >> 3) + (row & 3);
                int half = (row >> 2) & 1;
                #pragma unroll
                for (int e = 0; e < 4; e++)
                    Vf[rv * VF_STRIDE + 2 * (d0 + e) + half] = __uint_as_float(to_tf32(vv4[e]));
            }
        }
        __syncthreads();

        // ---- QK^T: 16x64 per warp via 128 HMMA tf32 ----
        float c[8][4];
        #pragma unroll
        for (int nt = 0; nt < 8; nt++)
            #pragma unroll
            for (int e = 0; e < 4; e++) c[nt][e] = 0.0f;

        #pragma unroll
        for (int kk = 0; kk < 16; kk++) {
            uint2 a02 = *(const uint2*)&Qs[(qb + g)     * QS_STRIDE + 8 * kk + 2 * tig];
            uint2 a13 = *(const uint2*)&Qs[(qb + g + 8) * QS_STRIDE + 8 * kk + 2 * tig];
            #pragma unroll
            for (int nt = 0; nt < 8; nt++) {
                uint2 b01 = *(const uint2*)&Ks[(8 * nt + g) * KS_STRIDE + 8 * kk + 2 * tig];
                mma_tf32(c[nt], a02.x, a13.x, a02.y, a13.y, b01.x, b01.y);
            }
        }

        // ---- mask + bias + online softmax on fragments ----
        float mx0 = -1e30f, mx1 = -1e30f;
        #pragma unroll
        for (int nt = 0; nt < 8; nt++) {
            int j0 = k0 + 8 * nt + 2 * tig;
            int j1 = j0 + 1;
            bool ok00 = (j0 <= i0) && ((j0 < NGLOBAL) || (j0 >= i0 - (LPRE - 1)));
            bool ok01 = (j1 <= i0) && ((j1 < NGLOBAL) || (j1 >= i0 - (LPRE - 1)));
            bool ok10 = (j0 <= i1) && ((j0 < NGLOBAL) || (j0 >= i1 - (LPRE - 1)));
            bool ok11 = (j1 <= i1) && ((j1 < NGLOBAL) || (j1 >= i1 - (LPRE - 1)));
            c[nt][0] = ok00 ? fmaf((float)(j0 - i0), LOG2E, c[nt][0]) : -1e30f;
            c[nt][1] = ok01 ? fmaf((float)(j1 - i0), LOG2E, c[nt][1]) : -1e30f;
            c[nt][2] = ok10 ? fmaf((float)(j0 - i1), LOG2E, c[nt][2]) : -1e30f;
            c[nt][3] = ok11 ? fmaf((float)(j1 - i1), LOG2E, c[nt][3]) : -1e30f;
            mx0 = fmaxf(mx0, fmaxf(c[nt][0], c[nt][1]));
            mx1 = fmaxf(mx1, fmaxf(c[nt][2], c[nt][3]));
        }
        mx0 = fmaxf(mx0, __shfl_xor_sync(0xffffffffu, mx0, 1));
        mx0 = fmaxf(mx0, __shfl_xor_sync(0xffffffffu, mx0, 2));
        mx1 = fmaxf(mx1, __shfl_xor_sync(0xffffffffu, mx1, 1));
        mx1 = fmaxf(mx1, __shfl_xor_sync(0xffffffffu, mx1, 2));

        float mn0 = fmaxf(m0, mx0), mn1 = fmaxf(m1, mx1);
        float sc0 = fexp2(m0 - mn0), sc1 = fexp2(m1 - mn1);
        float ps0 = 0.0f, ps1 = 0.0f;
        #pragma unroll
        for (int nt = 0; nt < 8; nt++) {
            #pragma unroll
            for (int e = 0; e < 2; e++) {
                int jl = 8 * nt + 2 * tig + e;
                int pc = phys_col(jl);
                u32 pb0 = to_tf32(fexp2(c[nt][e]     - mn0));
                u32 pb1 = to_tf32(fexp2(c[nt][2 + e] - mn1));
                ps0 += __uint_as_float(pb0);
                ps1 += __uint_as_float(pb1);
                Pt[(qb + g)     * PT_STRIDE + pc] = __uint_as_float(pb0);
                Pt[(qb + g + 8) * PT_STRIDE + pc] = __uint_as_float(pb1);
            }
        }
        ps0 += __shfl_xor_sync(0xffffffffu, ps0, 1);
        ps0 += __shfl_xor_sync(0xffffffffu, ps0, 2);
        ps1 += __shfl_xor_sync(0xffffffffu, ps1, 1);
        ps1 += __shfl_xor_sync(0xffffffffu, ps1, 2);

        l0 = l0 * sc0 + ps0;  m0 = mn0;
        l1 = l1 * sc1 + ps1;  m1 = mn1;
        #pragma unroll
        for (int nt = 0; nt < 16; nt++) {
            co[nt][0] *= sc0; co[nt][1] *= sc0;
            co[nt][2] *= sc1; co[nt][3] *= sc1;
        }
        __syncwarp();   // P rows are warp-private: warp-level fence suffices

        // ---- P x V: 16x128 per warp via 128 HMMA tf32 ----
        #pragma unroll
        for (int kk2 = 0; kk2 < 8; kk2++) {
            uint2 a02 = *(const uint2*)&Pt[(qb + g)     * PT_STRIDE + 8 * kk2 + 2 * tig];
            uint2 a13 = *(const uint2*)&Pt[(qb + g + 8) * PT_STRIDE + 8 * kk2 + 2 * tig];
            #pragma unroll
            for (int nt = 0; nt < 16; nt++) {
                uint2 b01 = *(const uint2*)&Vf[(4 * kk2 + tig) * VF_STRIDE + 2 * (8 * nt + g)];
                mma_tf32(co[nt], a02.x, a13.x, a02.y, a13.y, b01.x, b01.y);
            }
        }
        __syncwarp();   // PV reads of Pt done before next tile overwrites it
    }

    // ---- epilogue: write unnormalized partials for this split ----
    const size_t rowbase = (size_t)(sp * BMAX + b) * S;
    float2* o0 = (float2*)(g_Op + (rowbase + i0) * D);
    float2* o1 = (float2*)(g_Op + (rowbase + i1) * D);
    #pragma unroll
    for (int nt = 0; nt < 16; nt++) {
        o0[4 * nt + tig] = make_float2(co[nt][0], co[nt][1]);
        o1[4 * nt + tig] = make_float2(co[nt][2], co[nt][3]);
    }
    if (tig == 0) {
        g_Ml[rowbase + i0] = m0;  g_Ll[rowbase + i0] = l0;
        g_Ml[rowbase + i1] = m1;  g_Ll[rowbase + i1] = l1;
    }
}

__global__ void __launch_bounds__(256)
combine_kernel(float* __restrict__ O, int S) {
    const int d4pr  = D / 4;                       // float4 per row
    const int total = BMAX * S * d4pr;             // float4 units
    int idx = blockIdx.x * blockDim.x + threadIdx.x;
    if (idx >= total) return;
    int row = idx / d4pr;                          // b*S + i

    const size_t rstride = (size_t)BMAX * S;
    float ms[SP], ls[SP];
    float m = -1e30f;
    #pragma unroll
    for (int s = 0; s < SP; s++) {
        ms[s] = g_Ml[s * rstride + row];
        ls[s] = g_Ll[s * rstride + row];
        if (ls[s] > 0.0f) m = fmaxf(m, ms[s]);
    }
    const float4* Op4 = (const float4*)g_Op;
    float denom = 0.0f;
    float4 acc = make_float4(0.0f, 0.0f, 0.0f, 0.0f);
    #pragma unroll
    for (int s = 0; s < SP; s++) {
        if (ls[s] > 0.0f) {
            float wv = fexp2(ms[s] - m);
            denom = fmaf(wv, ls[s], denom);
            float4 o = Op4[(size_t)s * total + idx];
            acc.x = fmaf(wv, o.x, acc.x);
            acc.y = fmaf(wv, o.y, acc.y);
            acc.z = fmaf(wv, o.z, acc.z);
            acc.w = fmaf(wv, o.w, acc.w);
        }
    }
    float inv = 1.0f / denom;
    ((float4*)O)[idx] = make_float4(acc.x * inv, acc.y * inv, acc.z * inv, acc.w * inv);
}

extern "C" void kernel_launch(void* const* d_in, const int* in_sizes, int n_in,
                              void* d_out, int out_size) {
    const float* q = (const float*)d_in[0];
    const float* k = (const float*)d_in[1];
    const float* v = (const float*)d_in[2];
    float* o = (float*)d_out;

    const int B = 2;
    const int S = in_sizes[0] / (B * D);   // 8192

    size_t smem_bytes = (size_t)SMEM_FLOATS * sizeof(float);  // ~171 KB
    cudaFuncSetAttribute(lminf_kernel, cudaFuncAttributeMaxDynamicSharedMemorySize,
                         (int)smem_bytes);

    dim3 grid(S / TQ, B, SP);
    lminf_kernel<<<grid, NTHREADS, smem_bytes>>>(q, k, v, S);

    int total4 = B * S * (D / 4);
    combine_kernel<<<(total4 + 255) / 256, 256>>>(o, S);
}

// round 7
// speedup vs baseline: 1.1503x; 1.0284x over previous
#include <cuda_runtime.h>
#include <cstdint>

#define D 128
#define TQ 128
#define TK 64
#define NTHREADS 256
#define NGLOBAL 100
#define LPRE 2048
#define SP 4            // key-dimension splits (flash-decoding style)
#define BMAX 2
#define SMAX 8192

#define QS_STRIDE 136   // ≡8 mod 32: conflict-free v2 fragment LDS
#define KR_STRIDE 132   // raw rows padded 128->132 (16B-aligned rows, bank-spread)

#define QS_OFF 0
#define K0_OFF (TQ * QS_STRIDE)            // 17408
#define K1_OFF (K0_OFF + TK * KR_STRIDE)   // 25856
#define V0_OFF (K1_OFF + TK * KR_STRIDE)   // 34304
#define V1_OFF (V0_OFF + TK * KR_STRIDE)   // 42752
#define SMEM_FLOATS (V1_OFF + TK * KR_STRIDE)   // 51200 floats = 204.8 KB

typedef unsigned int u32;

// split-K scratch (static device globals: allocation-free)
__device__ float g_Op[(size_t)SP * BMAX * SMAX * D];   // unnormalized partial O
__device__ float g_Ml[SP * BMAX * SMAX];               // per-row running max (log2 domain)
__device__ float g_Ll[SP * BMAX * SMAX];               // per-row partial denom

__device__ __forceinline__ u32 to_tf32(float x) {
    u32 r;
    asm("cvt.rna.tf32.f32 %0, %1;" : "=r"(r) : "f"(x));
    return r;
}

__device__ __forceinline__ void mma_tf32(float c[4], u32 a0, u32 a1, u32 a2, u32 a3,
                                         u32 b0, u32 b1) {
    asm volatile(
        "mma.sync.aligned.m16n8k8.row.col.f32.tf32.tf32.f32 "
        "{%0,%1,%2,%3}, {%4,%5,%6,%7}, {%8,%9}, {%0,%1,%2,%3};"
        : "+f"(c[0]), "+f"(c[1]), "+f"(c[2]), "+f"(c[3])
        : "r"(a0), "r"(a1), "r"(a2), "r"(a3), "r"(b0), "r"(b1));
}

__device__ __forceinline__ void cp_async16(u32 dst_smem, const void* src) {
    asm volatile("cp.async.cg.shared.global [%0], [%1], 16;"
                 :: "r"(dst_smem), "l"(src));
}
__device__ __forceinline__ void cp_commit() {
    asm volatile("cp.async.commit_group;");
}
__device__ __forceinline__ void cp_wait_all_groups() {
    asm volatile("cp.async.wait_group 0;");
}

// column permutation for Q: fragment positions tig and tig+4 adjacent -> v2 LDS.
__device__ __forceinline__ int phys_col(int d) {
    return (d & ~7) | ((d & 3) << 1) | ((d >> 2) & 1);
}

// fast exp2 for x <= 0 (poly deg-6, rel err ~1e-5). Handles -1e30 sentinel -> ~0.
__device__ __forceinline__ float fexp2(float x) {
    x = fmaxf(x, -126.0f);
    int ni = __float2int_rd(x);
    float f = x - (float)ni;
    float p = 1.54035304e-4f;
    p = fmaf(p, f, 1.33335581e-3f);
    p = fmaf(p, f, 9.61812911e-3f);
    p = fmaf(p, f, 5.55041087e-2f);
    p = fmaf(p, f, 2.40226507e-1f);
    p = fmaf(p, f, 6.93147181e-1f);
    p = fmaf(p, f, 1.0f);
    return __int_as_float(__float_as_int(p) + (ni << 23));
}

__global__ void __launch_bounds__(NTHREADS, 1)
lminf_kernel(const float* __restrict__ Q, const float* __restrict__ K,
             const float* __restrict__ V, int S) {
    extern __shared__ float sm[];
    float* Qs = sm + QS_OFF;

    const int b   = blockIdx.y;
    const int q0  = blockIdx.x * TQ;
    const int sp  = blockIdx.z;
    const int tid = threadIdx.x;
    const int w    = tid >> 5;
    const int lane = tid & 31;
    const int g    = lane >> 2;   // group id 0..7
    const int tig  = lane & 3;    // thread-in-group 0..3
    const int qb   = 16 * w;      // warp's q-row base within tile
    const int slot = tig & 1;
    const int sA   = (lane & ~3) | (tig >> 1);        // shuffle src for col tig
    const int sB   = sA + 2;                           // shuffle src for col tig+4

    const float* Qg = Q + (size_t)b * S * D;
    const float* Kg = K + (size_t)b * S * D;
    const float* Vg = V + (size_t)b * S * D;

    const float QSCALE = 0.0883883476f * 1.44269504089f;  // 1/sqrt(128) * log2(e)
    const float LOG2E  = 1.44269504089f;

    // ---- enumerate visited tiles & take this split's contiguous chunk ----
    const int nTile = (q0 + TQ) / TK;
    int tLoc = 2;
    {
        int dd = q0 - (LPRE - 1) - TK;   // tile t skipped iff t>=2 && 64t <= dd
        if (dd >= 0) { int t = dd / TK + 1; if (t > 2) tLoc = t; }
    }
    const int NT  = 2 + (nTile - tLoc);
    const int it0 = (sp * NT) / SP;
    const int it1 = ((sp + 1) * NT) / SP;

    const u32 smem_u32 = (u32)__cvta_generic_to_shared(sm);

    // prefetch K/V tile `it` into buffer (it&1) via cp.async (raw fp32, padded rows)
    auto prefetch = [&](int it) {
        const int k0 = ((it < 2) ? it : (tLoc + it - 2)) * TK;
        const u32 kbuf = smem_u32 + ((it & 1) ? K1_OFF : K0_OFF) * 4;
        const u32 vbuf = smem_u32 + ((it & 1) ? V1_OFF : V0_OFF) * 4;
        const float* ksrc = Kg + (size_t)k0 * D;
        const float* vsrc = Vg + (size_t)k0 * D;
        #pragma unroll
        for (int c = 0; c < (TK * 32) / NTHREADS; c++) {
            int idx = tid + c * NTHREADS;
            int row = idx >> 5, c4 = idx & 31;
            u32 off = (u32)(row * KR_STRIDE + c4 * 4) * 4;
            cp_async16(kbuf + off, ksrc + row * D + c4 * 4);
            cp_async16(vbuf + off, vsrc + row * D + c4 * 4);
        }
        cp_commit();
    };

    if (it0 < it1) {
        prefetch(it0);
        // ---- load Q tile: tf32-rounded, pre-scaled, column-permuted ----
        const float4* src = (const float4*)(Qg + (size_t)q0 * D);
        #pragma unroll
        for (int it = 0; it < (TQ * 32) / NTHREADS; it++) {
            int idx = tid + it * NTHREADS;
            int row = idx >> 5, f4 = idx & 31;
            float4 v = src[idx];
            float vv[4] = {v.x * QSCALE, v.y * QSCALE, v.z * QSCALE, v.w * QSCALE};
            int d0 = f4 * 4;
            #pragma unroll
            for (int e = 0; e < 4; e++)
                Qs[row * QS_STRIDE + phys_col(d0 + e)] = __uint_as_float(to_tf32(vv[e]));
        }
    }

    float co[16][4];              // O accum: 16 dim-tiles x {r0d0,r0d1,r1d0,r1d1}
    #pragma unroll
    for (int nt = 0; nt < 16; nt++)
        #pragma unroll
        for (int e = 0; e < 4; e++) co[nt][e] = 0.0f;
    float m0 = -1e30f, m1 = -1e30f, l0 = 0.0f, l1 = 0.0f;

    const int i0 = q0 + qb + g;
    const int i1 = i0 + 8;

    for (int it = it0; it < it1; it++) {
        const int k0 = ((it < 2) ? it : (tLoc + it - 2)) * TK;
        const float* Kr = sm + ((it & 1) ? K1_OFF : K0_OFF);
        const float* Vr = sm + ((it & 1) ? V1_OFF : V0_OFF);

        cp_wait_all_groups();      // tile `it` resident
        __syncthreads();           // visible to all warps; prev compute done
        if (it + 1 < it1) prefetch(it + 1);   // overlaps compute below

        // ---- QK^T: 16x64 per warp via 128 HMMA tf32 ----
        float c[8][4];
        #pragma unroll
        for (int nt = 0; nt < 8; nt++)
            #pragma unroll
            for (int e = 0; e < 4; e++) c[nt][e] = 0.0f;

        #pragma unroll
        for (int kk = 0; kk < 16; kk++) {
            uint2 a02 = *(const uint2*)&Qs[(qb + g)     * QS_STRIDE + 8 * kk + 2 * tig];
            uint2 a13 = *(const uint2*)&Qs[(qb + g + 8) * QS_STRIDE + 8 * kk + 2 * tig];
            #pragma unroll
            for (int nt = 0; nt < 8; nt++) {
                const float* krow = Kr + (8 * nt + g) * KR_STRIDE + 8 * kk;
                u32 b0 = to_tf32(krow[tig]);
                u32 b1 = to_tf32(krow[tig + 4]);
                mma_tf32(c[nt], a02.x, a13.x, a02.y, a13.y, b0, b1);
            }
        }

        // ---- mask + bias + online softmax on fragments ----
        float mx0 = -1e30f, mx1 = -1e30f;
        #pragma unroll
        for (int nt = 0; nt < 8; nt++) {
            int j0 = k0 + 8 * nt + 2 * tig;
            int j1 = j0 + 1;
            bool ok00 = (j0 <= i0) && ((j0 < NGLOBAL) || (j0 >= i0 - (LPRE - 1)));
            bool ok01 = (j1 <= i0) && ((j1 < NGLOBAL) || (j1 >= i0 - (LPRE - 1)));
            bool ok10 = (j0 <= i1) && ((j0 < NGLOBAL) || (j0 >= i1 - (LPRE - 1)));
            bool ok11 = (j1 <= i1) && ((j1 < NGLOBAL) || (j1 >= i1 - (LPRE - 1)));
            c[nt][0] = ok00 ? fmaf((float)(j0 - i0), LOG2E, c[nt][0]) : -1e30f;
            c[nt][1] = ok01 ? fmaf((float)(j1 - i0), LOG2E, c[nt][1]) : -1e30f;
            c[nt][2] = ok10 ? fmaf((float)(j0 - i1), LOG2E, c[nt][2]) : -1e30f;
            c[nt][3] = ok11 ? fmaf((float)(j1 - i1), LOG2E, c[nt][3]) : -1e30f;
            mx0 = fmaxf(mx0, fmaxf(c[nt][0], c[nt][1]));
            mx1 = fmaxf(mx1, fmaxf(c[nt][2], c[nt][3]));
        }
        mx0 = fmaxf(mx0, __shfl_xor_sync(0xffffffffu, mx0, 1));
        mx0 = fmaxf(mx0, __shfl_xor_sync(0xffffffffu, mx0, 2));
        mx1 = fmaxf(mx1, __shfl_xor_sync(0xffffffffu, mx1, 1));
        mx1 = fmaxf(mx1, __shfl_xor_sync(0xffffffffu, mx1, 2));

        float mn0 = fmaxf(m0, mx0), mn1 = fmaxf(m1, mx1);
        float sc0 = fexp2(m0 - mn0), sc1 = fexp2(m1 - mn1);
        float ps0 = 0.0f, ps1 = 0.0f;
        #pragma unroll
        for (int nt = 0; nt < 8; nt++) {
            float p00 = __uint_as_float(to_tf32(fexp2(c[nt][0] - mn0)));
            float p01 = __uint_as_float(to_tf32(fexp2(c[nt][1] - mn0)));
            float p10 = __uint_as_float(to_tf32(fexp2(c[nt][2] - mn1)));
            float p11 = __uint_as_float(to_tf32(fexp2(c[nt][3] - mn1)));
            ps0 += p00 + p01;
            ps1 += p10 + p11;
            c[nt][0] = p00; c[nt][1] = p01; c[nt][2] = p10; c[nt][3] = p11;
        }
        ps0 += __shfl_xor_sync(0xffffffffu, ps0, 1);
        ps0 += __shfl_xor_sync(0xffffffffu, ps0, 2);
        ps1 += __shfl_xor_sync(0xffffffffu, ps1, 1);
        ps1 += __shfl_xor_sync(0xffffffffu, ps1, 2);

        l0 = l0 * sc0 + ps0;  m0 = mn0;
        l1 = l1 * sc1 + ps1;  m1 = mn1;
        #pragma unroll
        for (int nt = 0; nt < 16; nt++) {
            co[nt][0] *= sc0; co[nt][1] *= sc0;
            co[nt][2] *= sc1; co[nt][3] *= sc1;
        }

        // ---- P x V: C-fragment -> A-fragment via intra-quad shuffles, no smem ----
        #pragma unroll
        for (int kt = 0; kt < 8; kt++) {
            // A needs cols {tig, tig+4} of P; C holds cols {2tig, 2tig+1}.
            float v0 = __shfl_sync(0xffffffffu, c[kt][0], sA);
            float v1 = __shfl_sync(0xffffffffu, c[kt][1], sA);
            float v2 = __shfl_sync(0xffffffffu, c[kt][2], sA);
            float v3 = __shfl_sync(0xffffffffu, c[kt][3], sA);
            float w0 = __shfl_sync(0xffffffffu, c[kt][0], sB);
            float w1 = __shfl_sync(0xffffffffu, c[kt][1], sB);
            float w2 = __shfl_sync(0xffffffffu, c[kt][2], sB);
            float w3 = __shfl_sync(0xffffffffu, c[kt][3], sB);
            u32 a0 = __float_as_uint(slot ? v1 : v0);
            u32 a1 = __float_as_uint(slot ? v3 : v2);
            u32 a2 = __float_as_uint(slot ? w1 : w0);
            u32 a3 = __float_as_uint(slot ? w3 : w2);
            #pragma unroll
            for (int nt = 0; nt < 16; nt++) {
                const float* vrow = Vr + (8 * kt + tig) * KR_STRIDE + 8 * nt + g;
                u32 b0 = to_tf32(vrow[0]);
                u32 b1 = to_tf32(vrow[4 * KR_STRIDE]);
                mma_tf32(co[nt], a0, a1, a2, a3, b0, b1);
            }
        }
    }

    // ---- epilogue: write unnormalized partials for this split ----
    const size_t rowbase = (size_t)(sp * BMAX + b) * S;
    float2* o0 = (float2*)(g_Op + (rowbase + i0) * D);
    float2* o1 = (float2*)(g_Op + (rowbase + i1) * D);
    #pragma unroll
    for (int nt = 0; nt < 16; nt++) {
        o0[4 * nt + tig] = make_float2(co[nt][0], co[nt][1]);
        o1[4 * nt + tig] = make_float2(co[nt][2], co[nt][3]);
    }
    if (tig == 0) {
        g_Ml[rowbase + i0] = m0;  g_Ll[rowbase + i0] = l0;
        g_Ml[rowbase + i1] = m1;  g_Ll[rowbase + i1] = l1;
    }
}

__global__ void __launch_bounds__(256)
combine_kernel(float* __restrict__ O, int S) {
    const int d4pr  = D / 4;                       // float4 per row
    const int total = BMAX * S * d4pr;             // float4 units
    int idx = blockIdx.x * blockDim.x + threadIdx.x;
    if (idx >= total) return;
    int row = idx / d4pr;                          // b*S + i

    const size_t rstride = (size_t)BMAX * S;
    float ms[SP], ls[SP];
    float m = -1e30f;
    #pragma unroll
    for (int s = 0; s < SP; s++) {
        ms[s] = g_Ml[s * rstride + row];
        ls[s] = g_Ll[s * rstride + row];
        if (ls[s] > 0.0f) m = fmaxf(m, ms[s]);
    }
    const float4* Op4 = (const float4*)g_Op;
    float denom = 0.0f;
    float4 acc = make_float4(0.0f, 0.0f, 0.0f, 0.0f);
    #pragma unroll
    for (int s = 0; s < SP; s++) {
        if (ls[s] > 0.0f) {
            float wv = fexp2(ms[s] - m);
            denom = fmaf(wv, ls[s], denom);
            float4 o = Op4[(size_t)s * total + idx];
            acc.x = fmaf(wv, o.x, acc.x);
            acc.y = fmaf(wv, o.y, acc.y);
            acc.z = fmaf(wv, o.z, acc.z);
            acc.w = fmaf(wv, o.w, acc.w);
        }
    }
    float inv = 1.0f / denom;
    ((float4*)O)[idx] = make_float4(acc.x * inv, acc.y * inv, acc.z * inv, acc.w * inv);
}

extern "C" void kernel_launch(void* const* d_in, const int* in_sizes, int n_in,
                              void* d_out, int out_size) {
    const float* q = (const float*)d_in[0];
    const float* k = (const float*)d_in[1];
    const float* v = (const float*)d_in[2];
    float* o = (float*)d_out;

    const int B = 2;
    const int S = in_sizes[0] / (B * D);   // 8192

    size_t smem_bytes = (size_t)SMEM_FLOATS * sizeof(float);  // ~205 KB
    cudaFuncSetAttribute(lminf_kernel, cudaFuncAttributeMaxDynamicSharedMemorySize,
                         (int)smem_bytes);

    dim3 grid(S / TQ, B, SP);
    lminf_kernel<<<grid, NTHREADS, smem_bytes>>>(q, k, v, S);

    int total4 = B * S * (D / 4);
    combine_kernel<<<(total4 + 255) / 256, 256>>>(o, S);
}